// round 15
// baseline (speedup 1.0000x reference)
#include <cuda_runtime.h>
#include <cuda_bf16.h>
#include <math.h>
#include <stdint.h>

#define Dd 1024
#define Mm 8192
#define Hh 16
#define Bb 64

typedef __nv_bfloat16 bf16;

// ---------------- scratch (device globals) ----------------------------------
#define DA __device__ __align__(16)
DA bf16 s_WkT[Dd * 2 * Dd];
DA bf16 s_WvT[Dd * 2 * Dd];
DA bf16 s_Wik[Dd * 2 * Dd];
DA bf16 s_Wiv[Dd * 2 * Dd];
DA bf16 s_Wck[Dd * 2 * Dd];
DA bf16 s_Wcv[Dd * 2 * Dd];
DA bf16 s_keys[Mm * 2 * Dd];
DA bf16 s_vals[Mm * 2 * Dd];
DA bf16 s_kh[Mm * 2 * Dd];          // head-blocked: head h at h*128, [h(64)|l(64)]
DA bf16 s_vh2[2 * Mm * Dd];         // row-plane split: rows 0..Mm-1 = h, Mm.. = l
DA bf16 s_attn[Bb * Hh * 2 * Mm];
DA bf16 s_x[Bb * 2 * Dd];
DA bf16 s_Wq[Dd * 2 * Dd];
DA bf16 s_q[Bb * 2 * Dd];
DA bf16 s_Wiq[Dd * 2 * Dd];
DA bf16 s_qh[Bb * 2 * Dd];          // head-blocked
DA bf16 s_ctx[Bb * 2 * Dd];
DA bf16 s_outw[Dd * 2 * Dd];
DA bf16 s_gW1x[Dd * 2 * Dd];        // gW1 cols 0..D-1   as [h|l]
DA bf16 s_gW1m[Dd * 2 * Dd];        // gW1 cols D..2D-1  as [h|l]
DA bf16 s_g1[Bb * 2 * Dd];
DA bf16 s_gW2[Dd * 2 * Dd];
DA bf16 s_ms2[Bb * 2 * Dd];         // split of ms
DA bf16 s_gated2[Bb * 2 * Dd];      // split of gated
DA bf16 s_iW1x[2 * Dd * 2 * Dd];    // iW1 cols 0..D-1
DA bf16 s_iW1g[2 * Dd * 2 * Dd];    // iW1 cols D..2D-1
DA bf16 s_i1[Bb * 4 * Dd];
DA bf16 s_iW2[Dd * 4 * Dd];

DA float f_part[32 * Bb * Dd];      // split-K partials (shared, default stream)
DA float f_pc1[3 * Dd * Dd];        // combine partials (stream s1)
DA float f_pc2[3 * Dd * Dd];        // combine partials (stream s2)
DA float f_pg1[32 * Bb * Dd];       // gate-layer1 partials (x-part 0..15, ms-part 16..31)
DA float f_pi1[32 * Bb * 2 * Dd];   // out-layer1 partials
DA float f_scores[Bb * Hh * Mm];
DA float f_ms[Bb * Dd];
DA float f_bcv[Dd];

// ---------------- helpers ----------------------------------------------------
__device__ __forceinline__ uint32_t sptr(const void* p)
{
    return (uint32_t)__cvta_generic_to_shared(p);
}

__device__ __forceinline__ void cpasync16(const bf16* g, uint32_t s)
{
    asm volatile("cp.async.ca.shared.global [%0], [%1], 16;" :: "r"(s), "l"(g));
}

__device__ __forceinline__ void ldm4(uint32_t s, uint32_t& r0, uint32_t& r1,
                                     uint32_t& r2, uint32_t& r3)
{
    asm volatile("ldmatrix.sync.aligned.m8n8.x4.shared.b16 {%0,%1,%2,%3}, [%4];"
                 : "=r"(r0), "=r"(r1), "=r"(r2), "=r"(r3) : "r"(s));
}

__device__ __forceinline__ void ldm4t(uint32_t s, uint32_t& r0, uint32_t& r1,
                                      uint32_t& r2, uint32_t& r3)
{
    asm volatile("ldmatrix.sync.aligned.m8n8.x4.trans.shared.b16 {%0,%1,%2,%3}, [%4];"
                 : "=r"(r0), "=r"(r1), "=r"(r2), "=r"(r3) : "r"(s));
}

__device__ __forceinline__ void mma16816(float* c, const uint32_t* a, const uint32_t* b)
{
    asm volatile(
        "mma.sync.aligned.m16n8k16.row.col.f32.bf16.bf16.f32 "
        "{%0,%1,%2,%3}, {%4,%5,%6,%7}, {%8,%9}, {%0,%1,%2,%3};"
        : "+f"(c[0]), "+f"(c[1]), "+f"(c[2]), "+f"(c[3])
        : "r"(a[0]), "r"(a[1]), "r"(a[2]), "r"(a[3]), "r"(b[0]), "r"(b[1]));
}

// write split of v.
// smode 0: col-plane [h|l]; 1: head-blocked; 2: row-plane with loOff
__device__ __forceinline__ void write_split(bf16* sout, long rr, int cc, int ldc,
                                            int smode, long loOff, float v)
{
    bf16 h = __float2bfloat16(v);
    bf16 l = __float2bfloat16(v - __bfloat162float(h));
    if (smode == 2) {
        long b = rr * (long)ldc + cc;
        sout[b] = h; sout[loOff + b] = l;
    } else if (smode == 0) {
        long rb = rr * 2 * (long)ldc;
        sout[rb + cc] = h; sout[rb + ldc + cc] = l;
    } else {
        int hd = cc >> 6, j = cc & 63;
        long base = rr * 2 * (long)ldc + hd * 128 + j;
        sout[base] = h; sout[base + 64] = l;
    }
}

// ---------------- bf16-split HMMA GEMM (TN), phase-tripled ---------------------
template <int BM, int BN, int TMW, int TNW, int NTH, bool PART, bool TRB>
__global__ void __launch_bounds__(NTH) mma_gemm(
    const bf16* __restrict__ A, const bf16* __restrict__ B, float* __restrict__ C,
    int K1, int lda, int ldb, int ldc,
    long sA, long sB, long sC, int nsplit, long sPart, float alpha,
    const float* __restrict__ bias, int act, const float* __restrict__ mul,
    bf16* __restrict__ sout, int smode, long loOff)
{
    constexpr int BK = 32, SK = 40, SKN = 72;
    constexpr int WMn = BM / TMW;
    constexpr int WNn = BN / TNW;
    static_assert(WMn * WNn * 32 == NTH, "warp layout");
    constexpr int MI = TMW / 16, NI = TNW / 8;
    static_assert((NI & 1) == 0, "NI even");
    constexpr int CA = BM * 4 / NTH;
    constexpr int CBn = TRB ? (BK * BN / 8 / NTH) : (BN * 4 / NTH);
    constexpr int BSZ = TRB ? (BK * SKN) : (BN * SK);

    extern __shared__ bf16 dsm[];
    bf16* As = dsm;
    bf16* Bs = dsm + 3 * BM * SK;

    const int tid = threadIdx.x;
    const int lane = tid & 31;
    const int warp = tid >> 5;
    const int wm = (warp % WMn) * TMW;
    const int wn = (warp / WMn) * TNW;

    const long z = blockIdx.z;
    const long batch = z / nsplit;
    const int split = (int)(z % nsplit);
    A += batch * sA;
    B += batch * sB;
    C += batch * sC;

    const int NTP = K1 / BK;
    const int NT = 3 * NTP;
    const int TPS = NT / nsplit;
    const int t0 = split * TPS;
    const int m0 = blockIdx.y * BM;
    const int n0 = blockIdx.x * BN;

    float acc[MI][NI][4];
#pragma unroll
    for (int i = 0; i < MI; i++)
#pragma unroll
        for (int j = 0; j < NI; j++)
#pragma unroll
            for (int q = 0; q < 4; q++) acc[i][j][q] = 0.0f;

    auto loadT = [&](int buf, int t) {
        const int p = t / NTP;
        const int ktp = t - p * NTP;
        const int Acol = ktp * BK + (p == 2 ? K1 : 0);
        bf16* Abuf = As + buf * BM * SK;
        bf16* Bbuf = Bs + buf * BSZ;
#pragma unroll
        for (int i = 0; i < CA; i++) {
            int cid = tid + i * NTH;
            int r = cid >> 2, c = (cid & 3) * 8;
            cpasync16(A + (long)(m0 + r) * lda + Acol + c, sptr(&Abuf[r * SK + c]));
        }
        if (TRB) {
            const int Brow = ktp * BK + (p == 1 ? K1 : 0);
#pragma unroll
            for (int i = 0; i < CBn; i++) {
                int cid = tid + i * NTH;
                int k = cid / (BN / 8);
                int n = (cid % (BN / 8)) * 8;
                cpasync16(B + (long)(Brow + k) * ldb + n0 + n, sptr(&Bbuf[k * SKN + n]));
            }
        } else {
            const int Bcol = ktp * BK + (p == 1 ? K1 : 0);
#pragma unroll
            for (int i = 0; i < CBn; i++) {
                int cid = tid + i * NTH;
                int r = cid >> 2, c = (cid & 3) * 8;
                cpasync16(B + (long)(n0 + r) * ldb + Bcol + c, sptr(&Bbuf[r * SK + c]));
            }
        }
        asm volatile("cp.async.commit_group;");
    };

    loadT(0, t0);
    loadT(1, t0 + 1);

    for (int i = 0; i < TPS; i++) {
        const int s = i % 3;
        if (i + 1 < TPS) asm volatile("cp.async.wait_group 1;");
        else             asm volatile("cp.async.wait_group 0;");
        __syncthreads();
        if (i + 2 < TPS) loadT((i + 2) % 3, t0 + i + 2);

        bf16* Abuf = As + s * BM * SK;
        bf16* Bbuf = Bs + s * BSZ;
#pragma unroll
        for (int ki = 0; ki < 2; ki++) {
            uint32_t a[MI][4], b[NI][2];
#pragma unroll
            for (int mi = 0; mi < MI; mi++) {
                int row = wm + mi * 16 + (lane & 15);
                int col = ki * 16 + (lane >> 4) * 8;
                ldm4(sptr(&Abuf[row * SK + col]),
                     a[mi][0], a[mi][1], a[mi][2], a[mi][3]);
            }
#pragma unroll
            for (int nj = 0; nj < NI; nj += 2) {
                uint32_t r0, r1, r2, r3;
                if (TRB) {
                    int rowk = ki * 16 + ((lane >> 4) << 3) + (lane & 7);
                    int coln = wn + nj * 8 + (((lane >> 3) & 1) << 3);
                    ldm4t(sptr(&Bbuf[rowk * SKN + coln]), r0, r1, r2, r3);
                } else {
                    int row = wn + nj * 8 + (lane & 15);
                    int col = ki * 16 + (lane >> 4) * 8;
                    ldm4(sptr(&Bbuf[row * SK + col]), r0, r1, r2, r3);
                }
                b[nj][0] = r0;     b[nj][1] = r2;
                b[nj + 1][0] = r1; b[nj + 1][1] = r3;
            }
#pragma unroll
            for (int mi = 0; mi < MI; mi++)
#pragma unroll
                for (int nj = 0; nj < NI; nj++)
                    mma16816(acc[mi][nj], a[mi], b[nj]);
        }
    }

    // ---- epilogue
#pragma unroll
    for (int mi = 0; mi < MI; mi++) {
#pragma unroll
        for (int nj = 0; nj < NI; nj++) {
            const int r = m0 + wm + mi * 16 + (lane >> 2);
            const int c = n0 + wn + nj * 8 + (lane & 3) * 2;
#pragma unroll
            for (int q = 0; q < 4; q++) {
                const int rr = r + (q >> 1) * 8;
                const int cc = c + (q & 1);
                float v = acc[mi][nj][q] * alpha;
                if (PART) {
                    C[(long)split * sPart + (long)rr * ldc + cc] = v;
                } else {
                    if (bias) v += __ldg(&bias[cc]);
                    if (act == 1) v = fmaxf(v, 0.0f);
                    else if (act == 2) v = 1.0f / (1.0f + expf(-v));
                    if (mul) v *= mul[(long)rr * ldc + cc];
                    if (C) C[(long)rr * ldc + cc] = v;
                    if (sout) write_split(sout, rr, cc, ldc, smode, loOff, v);
                }
            }
        }
    }
}

// ---------------- finalize: sum split-K partials + epilogue --------------------
__global__ void fin_sum_k(const float* __restrict__ part, float* __restrict__ fout,
                          bf16* __restrict__ sout, long n, int Kc,
                          int nsplit, long sPart,
                          const float* __restrict__ bias, int act,
                          const float* __restrict__ mul, int smode)
{
    long i = (long)blockIdx.x * 256 + threadIdx.x;
    if (i >= n) return;
    long r = i / Kc;
    int c = (int)(i % Kc);
    float v = 0.0f;
    for (int s = 0; s < nsplit; s++) v += part[s * sPart + i];
    if (bias) v += bias[c];
    if (act == 1) v = fmaxf(v, 0.0f);
    else if (act == 2) v = 1.0f / (1.0f + expf(-v));
    if (mul) v *= mul[i];
    if (fout) fout[i] = v;
    if (sout) write_split(sout, r, c, Kc, smode, 0, v);
}

// ---------------- conversion kernels -----------------------------------------
__global__ void split2_k(const float* __restrict__ in, bf16* __restrict__ out,
                         int R, int K, int ldin)
{
    long g = (long)blockIdx.x * 256 + threadIdx.x;
    if (g >= (long)R * K / 4) return;
    long i = g * 4;
    int r = (int)(i / K), k = (int)(i % K);
    float4 xv = *(const float4*)&in[(long)r * ldin + k];
    float xs[4] = {xv.x, xv.y, xv.z, xv.w};
    bf16 hs[4], ls[4];
#pragma unroll
    for (int j = 0; j < 4; j++) {
        hs[j] = __float2bfloat16(xs[j]);
        ls[j] = __float2bfloat16(xs[j] - __bfloat162float(hs[j]));
    }
    bf16* o = out + (long)r * 2 * K;
    *(uint2*)&o[k] = *(uint2*)hs;
    *(uint2*)&o[K + k] = *(uint2*)ls;
}

// column-split: in R x 2K fp32 -> out1 gets cols [0,K) as [h|l], out2 cols [K,2K)
__global__ void splitcol2_k(const float* __restrict__ in, bf16* __restrict__ out1,
                            bf16* __restrict__ out2, int R, int K)
{
    long i = (long)blockIdx.x * 256 + threadIdx.x;
    if (i >= (long)R * 2 * K) return;
    int r = (int)(i / (2 * K)), c = (int)(i % (2 * K));
    float x = in[i];
    bf16 h = __float2bfloat16(x);
    bf16 l = __float2bfloat16(x - __bfloat162float(h));
    bf16* o = (c < K) ? out1 : out2;
    int cc = (c < K) ? c : c - K;
    o[(long)r * 2 * K + cc] = h;
    o[(long)r * 2 * K + K + cc] = l;
}

__global__ void tsplit2_k(const float* __restrict__ in, bf16* __restrict__ out,
                          int Kr, int Nc)
{
    __shared__ float t[32][33];
    int k0 = blockIdx.x * 32, n0 = blockIdx.y * 32;
    int tx = threadIdx.x, ty = threadIdx.y;
#pragma unroll
    for (int i = 0; i < 32; i += 8)
        t[ty + i][tx] = in[(long)(k0 + ty + i) * Nc + n0 + tx];
    __syncthreads();
#pragma unroll
    for (int i = 0; i < 32; i += 8) {
        int n = n0 + ty + i, k = k0 + tx;
        float x = t[tx][ty + i];
        bf16 h = __float2bfloat16(x);
        bf16 l = __float2bfloat16(x - __bfloat162float(h));
        bf16* o = out + (long)n * 2 * Kr + k;
        o[0] = h; o[Kr] = l;
    }
}

// ---------------- misc kernels (fp32) ----------------------------------------
__global__ void bias_combine_k(const float* __restrict__ W, const float* __restrict__ b1,
                               const float* __restrict__ b2, float* __restrict__ out)
{
    const int row = blockIdx.x * blockDim.y + threadIdx.y;
    const int lane = threadIdx.x;
    float s = 0.0f;
    for (int c = lane; c < Dd; c += 32) s += W[row * Dd + c] * b1[c];
#pragma unroll
    for (int o = 16; o; o >>= 1) s += __shfl_down_sync(0xffffffffu, s, o);
    if (lane == 0) out[row] = s + b2[row];
}

// softmax (register-cached) + fused [h|l] col-plane split
__global__ void softmax_split2_k(const float* __restrict__ s, bf16* __restrict__ sout)
{
    const float* row = s + (size_t)blockIdx.x * Mm;
    bf16* ob = sout + (size_t)blockIdx.x * 2 * Mm;
    __shared__ float red[256];
    const int t = threadIdx.x;
    float v[Mm / 256];
    float mx = -1e30f;
#pragma unroll
    for (int j = 0; j < Mm / 256; j++) {
        v[j] = row[t + j * 256];
        mx = fmaxf(mx, v[j]);
    }
    red[t] = mx;
    __syncthreads();
    for (int o = 128; o; o >>= 1) { if (t < o) red[t] = fmaxf(red[t], red[t + o]); __syncthreads(); }
    mx = red[0];
    __syncthreads();
    float sum = 0.0f;
#pragma unroll
    for (int j = 0; j < Mm / 256; j++) { v[j] = expf(v[j] - mx); sum += v[j]; }
    red[t] = sum;
    __syncthreads();
    for (int o = 128; o; o >>= 1) { if (t < o) red[t] += red[t + o]; __syncthreads(); }
    const float inv = 1.0f / red[0];
#pragma unroll
    for (int j = 0; j < Mm / 256; j++) {
        float w = v[j] * inv;
        bf16 h = __float2bfloat16(w);
        bf16 l = __float2bfloat16(w - __bfloat162float(h));
        ob[t + j * 256] = h;
        ob[Mm + t + j * 256] = l;
    }
}

// ---------------- launch ------------------------------------------------------
#define SYM(v, g) cudaGetSymbolAddress((void**)&v, g)
#define GRD(n) dim3((unsigned)(((long)(n) + 255) / 256))
#define SMEM_TN(BM, BN) (3 * ((BM) * 40 + (BN) * 40) * (int)sizeof(bf16))
#define SMEM_TR(BM)     (3 * ((BM) * 40 + 32 * 72) * (int)sizeof(bf16))

extern "C" void kernel_launch(void* const* d_in, const int* in_sizes, int n_in,
                              void* d_out, int out_size)
{
    (void)in_sizes; (void)n_in; (void)out_size;
    const float* x    = (const float*)d_in[0];
    const float* mk   = (const float*)d_in[1];
    const float* mv   = (const float*)d_in[2];
    const float* Wq   = (const float*)d_in[3];
    const float* bq   = (const float*)d_in[4];
    const float* Wk   = (const float*)d_in[5];
    const float* bk   = (const float*)d_in[6];
    const float* Wv   = (const float*)d_in[7];
    const float* bv   = (const float*)d_in[8];
    const float* ipw  = (const float*)d_in[9];
    const float* ipb  = (const float*)d_in[10];
    const float* outw = (const float*)d_in[11];
    const float* outb = (const float*)d_in[12];
    const float* gW1  = (const float*)d_in[13];
    const float* gb1  = (const float*)d_in[14];
    const float* gW2  = (const float*)d_in[15];
    const float* gb2  = (const float*)d_in[16];
    const float* iW1  = (const float*)d_in[17];
    const float* ib1  = (const float*)d_in[18];
    const float* iW2  = (const float*)d_in[19];
    const float* ib2  = (const float*)d_in[20];
    float* out = (float*)d_out;

    const float* Wiq = ipw;
    const float* Wik = ipw + Dd * Dd;
    const float* Wiv = ipw + 2 * Dd * Dd;
    const float* biq = ipb;
    const float* biv = ipb + 2 * Dd;

    bf16 *pWkT, *pWvT, *pWik, *pWiv, *pWck, *pWcv, *pkeys, *pvals, *pkh, *pvh2, *pattn;
    bf16 *px, *pWq, *pq, *pWiq, *pqh, *pctx, *poutw, *pgW1x, *pgW1m, *pg1, *pgW2;
    bf16 *pms, *pgated, *piW1x, *piW1g, *pi1, *piW2;
    float *fpart, *fpc1, *fpc2, *fpg1, *fpi1, *fsc, *fms, *fbcv;

    SYM(pWkT, s_WkT); SYM(pWvT, s_WvT); SYM(pWik, s_Wik); SYM(pWiv, s_Wiv);
    SYM(pWck, s_Wck); SYM(pWcv, s_Wcv); SYM(pkeys, s_keys); SYM(pvals, s_vals);
    SYM(pkh, s_kh); SYM(pvh2, s_vh2); SYM(pattn, s_attn);
    SYM(px, s_x); SYM(pWq, s_Wq); SYM(pq, s_q); SYM(pWiq, s_Wiq); SYM(pqh, s_qh);
    SYM(pctx, s_ctx); SYM(poutw, s_outw); SYM(pgW1x, s_gW1x); SYM(pgW1m, s_gW1m);
    SYM(pg1, s_g1); SYM(pgW2, s_gW2); SYM(pms, s_ms2); SYM(pgated, s_gated2);
    SYM(piW1x, s_iW1x); SYM(piW1g, s_iW1g); SYM(pi1, s_i1); SYM(piW2, s_iW2);
    SYM(fpart, f_part); SYM(fpc1, f_pc1); SYM(fpc2, f_pc2);
    SYM(fpg1, f_pg1); SYM(fpi1, f_pi1);
    SYM(fsc, f_scores); SYM(fms, f_ms); SYM(fbcv, f_bcv);

    cudaFuncSetAttribute((const void*)mma_gemm<128, 128, 32, 64, 256, false, false>,
                         cudaFuncAttributeMaxDynamicSharedMemorySize, SMEM_TN(128, 128));
    cudaFuncSetAttribute((const void*)mma_gemm<128, 128, 32, 64, 256, true, false>,
                         cudaFuncAttributeMaxDynamicSharedMemorySize, SMEM_TN(128, 128));
    cudaFuncSetAttribute((const void*)mma_gemm<64, 128, 32, 32, 256, true, false>,
                         cudaFuncAttributeMaxDynamicSharedMemorySize, SMEM_TN(64, 128));
    cudaFuncSetAttribute((const void*)mma_gemm<64, 128, 32, 32, 256, false, false>,
                         cudaFuncAttributeMaxDynamicSharedMemorySize, SMEM_TN(64, 128));
    cudaFuncSetAttribute((const void*)mma_gemm<64, 64, 32, 16, 256, true, true>,
                         cudaFuncAttributeMaxDynamicSharedMemorySize, SMEM_TR(64));

    static cudaStream_t s1 = nullptr, s2 = nullptr;
    static cudaEvent_t eFork = nullptr, eK = nullptr, eV = nullptr;
    if (!s1) {
        cudaStreamCreateWithFlags(&s1, cudaStreamNonBlocking);
        cudaStreamCreateWithFlags(&s2, cudaStreamNonBlocking);
        cudaEventCreateWithFlags(&eFork, cudaEventDisableTiming);
        cudaEventCreateWithFlags(&eK, cudaEventDisableTiming);
        cudaEventCreateWithFlags(&eV, cudaEventDisableTiming);
    }

    const dim3 blk(256);
    const dim3 tb(32, 8);
    const long sPsm = (long)Bb * Dd;
    const long sPi1 = (long)Bb * 2 * Dd;
    const long sPcb = (long)Dd * Dd;

    // ---- fork -------------------------------------------------------------------
    cudaEventRecord(eFork, 0);
    cudaStreamWaitEvent(s1, eFork, 0);
    cudaStreamWaitEvent(s2, eFork, 0);

    // ---- s1: K chain (softmax shift-invariance: kh needs no bias) ---------------
    tsplit2_k<<<dim3(Dd / 32, Dd / 32), tb, 0, s1>>>(Wk, pWkT, Dd, Dd);
    split2_k<<<GRD(Dd * Dd / 4), blk, 0, s1>>>(Wik, pWik, Dd, Dd, Dd);
    split2_k<<<GRD((long)Mm * Dd / 4), blk, 0, s1>>>(mk, pkeys, Mm, Dd, Dd);
    mma_gemm<128, 128, 32, 64, 256, true, false><<<dim3(8, 8, 3), blk, SMEM_TN(128, 128), s1>>>(
        pWik, pWkT, fpc1, Dd, 2 * Dd, 2 * Dd, Dd, 0, 0, 0, 3, sPcb, 1.0f,
        nullptr, 0, nullptr, nullptr, 0, 0);
    fin_sum_k<<<GRD(Dd * Dd), blk, 0, s1>>>(fpc1, nullptr, pWck, (long)Dd * Dd, Dd,
                                            3, sPcb, nullptr, 0, nullptr, 0);
    mma_gemm<128, 128, 32, 64, 256, false, false><<<dim3(8, 64, 1), blk, SMEM_TN(128, 128), s1>>>(
        pkeys, pWck, nullptr, Dd, 2 * Dd, 2 * Dd, Dd, 0, 0, 0, 1, 0, 1.0f,
        nullptr, 0, nullptr, pkh, 1, 0);
    cudaEventRecord(eK, s1);

    // ---- s2: V chain (bcv deferred to ctx finalize; sum(attn)=1) -----------------
    tsplit2_k<<<dim3(Dd / 32, Dd / 32), tb, 0, s2>>>(Wv, pWvT, Dd, Dd);
    split2_k<<<GRD(Dd * Dd / 4), blk, 0, s2>>>(Wiv, pWiv, Dd, Dd, Dd);
    split2_k<<<GRD((long)Mm * Dd / 4), blk, 0, s2>>>(mv, pvals, Mm, Dd, Dd);
    mma_gemm<128, 128, 32, 64, 256, true, false><<<dim3(8, 8, 3), blk, SMEM_TN(128, 128), s2>>>(
        pWiv, pWvT, fpc2, Dd, 2 * Dd, 2 * Dd, Dd, 0, 0, 0, 3, sPcb, 1.0f,
        nullptr, 0, nullptr, nullptr, 0, 0);
    fin_sum_k<<<GRD(Dd * Dd), blk, 0, s2>>>(fpc2, nullptr, pWcv, (long)Dd * Dd, Dd,
                                            3, sPcb, nullptr, 0, nullptr, 0);
    mma_gemm<128, 128, 32, 64, 256, false, false><<<dim3(8, 64, 1), blk, SMEM_TN(128, 128), s2>>>(
        pvals, pWcv, nullptr, Dd, 2 * Dd, 2 * Dd, Dd, 0, 0, 0, 1, 0, 1.0f,
        nullptr, 0, nullptr, pvh2, 2, (long)Mm * Dd);
    cudaEventRecord(eV, s2);

    // ---- origin: weight splits, x-part precomputes, q/qh chain --------------------
    bias_combine_k<<<Dd / 8, tb>>>(Wiv, bv, biv, fbcv);
    split2_k<<<GRD(Bb * Dd / 4), blk>>>(x, px, Bb, Dd, Dd);
    split2_k<<<GRD(Dd * Dd / 4), blk>>>(Wq, pWq, Dd, Dd, Dd);
    split2_k<<<GRD(Dd * Dd / 4), blk>>>(Wiq, pWiq, Dd, Dd, Dd);
    split2_k<<<GRD(Dd * Dd / 4), blk>>>(outw, poutw, Dd, Dd, Dd);
    splitcol2_k<<<GRD(Dd * 2 * Dd), blk>>>(gW1, pgW1x, pgW1m, Dd, Dd);
    split2_k<<<GRD(Dd * Dd / 4), blk>>>(gW2, pgW2, Dd, Dd, Dd);
    splitcol2_k<<<GRD(2 * Dd * 2 * Dd), blk>>>(iW1, piW1x, piW1g, 2 * Dd, Dd);
    split2_k<<<GRD(Dd * 2 * Dd / 4), blk>>>(iW2, piW2, Dd, 2 * Dd, 2 * Dd);

    // x-part of gate layer1 -> f_pg1 slots 0..15
    mma_gemm<64, 128, 32, 32, 256, true, false><<<dim3(8, 1, 16), blk, SMEM_TN(64, 128)>>>(
        px, pgW1x, fpg1, Dd, 2 * Dd, 2 * Dd, Dd, 0, 0, 0, 16, sPsm, 1.0f,
        nullptr, 0, nullptr, nullptr, 0, 0);
    // x-part of out layer1 -> f_pi1 slots 0..15
    mma_gemm<64, 128, 32, 32, 256, true, false><<<dim3(16, 1, 16), blk, SMEM_TN(64, 128)>>>(
        px, piW1x, fpi1, Dd, 2 * Dd, 2 * Dd, 2 * Dd, 0, 0, 0, 16, sPi1, 1.0f,
        nullptr, 0, nullptr, nullptr, 0, 0);

    // q / qh
    mma_gemm<64, 128, 32, 32, 256, true, false><<<dim3(8, 1, 16), blk, SMEM_TN(64, 128)>>>(
        px, pWq, fpart, Dd, 2 * Dd, 2 * Dd, Dd, 0, 0, 0, 16, sPsm, 1.0f,
        nullptr, 0, nullptr, nullptr, 0, 0);
    fin_sum_k<<<GRD(Bb * Dd), blk>>>(fpart, nullptr, pq, Bb * Dd, Dd, 16, sPsm,
                                     bq, 0, nullptr, 0);
    mma_gemm<64, 128, 32, 32, 256, true, false><<<dim3(8, 1, 16), blk, SMEM_TN(64, 128)>>>(
        pq, pWiq, fpart, Dd, 2 * Dd, 2 * Dd, Dd, 0, 0, 0, 16, sPsm, 1.0f,
        nullptr, 0, nullptr, nullptr, 0, 0);
    fin_sum_k<<<GRD(Bb * Dd), blk>>>(fpart, nullptr, pqh, Bb * Dd, Dd, 16, sPsm,
                                     biq, 0, nullptr, 1);

    // ---- join K: scores + softmax --------------------------------------------------
    cudaStreamWaitEvent(0, eK, 0);
    mma_gemm<64, 128, 32, 32, 256, false, false><<<dim3(Mm / 128, 1, Hh), blk, SMEM_TN(64, 128)>>>(
        pqh, pkh, fsc, 64, 2 * Dd, 2 * Dd, Hh * Mm,
        128, 128, Mm, 1, 0, 0.125f, nullptr, 0, nullptr, nullptr, 0, 0);
    softmax_split2_k<<<Bb * Hh, blk>>>(fsc, pattn);

    // ---- join V: ctx (bcv applied in finalize) ---------------------------------------
    cudaStreamWaitEvent(0, eV, 0);
    mma_gemm<64, 64, 32, 16, 256, true, true><<<dim3(1, 1, Hh * 32), blk, SMEM_TR(64)>>>(
        pattn, pvh2, fpart, Mm, Hh * 2 * Mm, Dd, Dd,
        2 * Mm, 64, 64, 32, sPsm, 1.0f, nullptr, 0, nullptr, nullptr, 0, 0);
    fin_sum_k<<<GRD(Bb * Dd), blk>>>(fpart, nullptr, pctx, Bb * Dd, Dd, 32, sPsm,
                                     fbcv, 0, nullptr, 0);

    // ---- ms (fp32 + split out) ---------------------------------------------------------
    mma_gemm<64, 128, 32, 32, 256, true, false><<<dim3(8, 1, 16), blk, SMEM_TN(64, 128)>>>(
        pctx, poutw, fpart, Dd, 2 * Dd, 2 * Dd, Dd, 0, 0, 0, 16, sPsm, 1.0f,
        nullptr, 0, nullptr, nullptr, 0, 0);
    fin_sum_k<<<GRD(Bb * Dd), blk>>>(fpart, fms, pms, Bb * Dd, Dd, 16, sPsm,
                                     outb, 0, nullptr, 0);

    // ---- gate: ms-part -> slots 16..31, then fin over 32 slots -------------------------
    mma_gemm<64, 128, 32, 32, 256, true, false><<<dim3(8, 1, 16), blk, SMEM_TN(64, 128)>>>(
        pms, pgW1m, fpg1 + 16 * sPsm, Dd, 2 * Dd, 2 * Dd, Dd, 0, 0, 0, 16, sPsm, 1.0f,
        nullptr, 0, nullptr, nullptr, 0, 0);
    fin_sum_k<<<GRD(Bb * Dd), blk>>>(fpg1, nullptr, pg1, Bb * Dd, Dd, 32, sPsm,
                                     gb1, 1, nullptr, 0);
    mma_gemm<64, 128, 32, 32, 256, true, false><<<dim3(8, 1, 16), blk, SMEM_TN(64, 128)>>>(
        pg1, pgW2, fpart, Dd, 2 * Dd, 2 * Dd, Dd, 0, 0, 0, 16, sPsm, 1.0f,
        nullptr, 0, nullptr, nullptr, 0, 0);
    fin_sum_k<<<GRD(Bb * Dd), blk>>>(fpart, nullptr, pgated, Bb * Dd, Dd, 16, sPsm,
                                     gb2, 2, fms, 0);

    // ---- out: gated-part -> slots 16..31, fin, final GEMM -------------------------------
    mma_gemm<64, 128, 32, 32, 256, true, false><<<dim3(16, 1, 16), blk, SMEM_TN(64, 128)>>>(
        pgated, piW1g, fpi1 + 16 * sPi1, Dd, 2 * Dd, 2 * Dd, 2 * Dd, 0, 0, 0, 16, sPi1, 1.0f,
        nullptr, 0, nullptr, nullptr, 0, 0);
    fin_sum_k<<<GRD(Bb * 2 * Dd), blk>>>(fpi1, nullptr, pi1, Bb * 2 * Dd, 2 * Dd, 32, sPi1,
                                         ib1, 1, nullptr, 0);
    mma_gemm<64, 128, 32, 32, 256, true, false><<<dim3(8, 1, 16), blk, SMEM_TN(64, 128)>>>(
        pi1, piW2, fpart, 2 * Dd, 4 * Dd, 4 * Dd, Dd, 0, 0, 0, 16, sPsm, 1.0f,
        nullptr, 0, nullptr, nullptr, 0, 0);
    fin_sum_k<<<GRD(Bb * Dd), blk>>>(fpart, out, nullptr, Bb * Dd, Dd, 16, sPsm,
                                     ib2, 0, nullptr, 0);
}